// round 2
// baseline (speedup 1.0000x reference)
#include <cuda_runtime.h>
#include <math.h>

// ---------------- problem constants ----------------
constexpr int V_  = 32000;
constexpr int E_  = 256;
constexpr int H_  = 512;
constexpr int LAT_= 100;
constexpr int NL_ = 3;
constexpr int B_  = 128;
constexpr int S_  = 32;
constexpr int BH_ = B_ * H_;

// ---------------- persistent device state ----------------
// h needs double buffering: the recurrent GEMM reads the full old h row while
// other blocks write the new h. c is touched elementwise (read+write by the
// same thread) so a single buffer is fine.
__device__ float g_hbuf[2][NL_ * BH_];
__device__ float g_cbuf[NL_ * BH_];
__device__ int   g_tok[B_];
__device__ unsigned long long g_arg[B_];

__device__ __forceinline__ float sigf(float x) { return 1.0f / (1.0f + expf(-x)); }

// order-preserving float -> uint transform (finite values)
__device__ __forceinline__ unsigned int fkey(float f) {
    unsigned int u = __float_as_uint(f);
    return (u & 0x80000000u) ? ~u : (u | 0x80000000u);
}

// ---------------- init: h0 = tanh(noise @ W_lat^T + b_lat) ----------------
// NOTE: reference reshapes the (B, NL*H) result to (NL, B, H) by flat
// reinterpretation (torch .view semantics). We write the flat buffer at
// index row*NL*H + col and later read it as [l*B*H + b*H + h] — identical
// flat layout, so no shuffling needed.
__global__ void init_kernel(const float* __restrict__ noise,
                            const float* __restrict__ W_lat,
                            const float* __restrict__ b_lat) {
    int j = blockIdx.x * blockDim.x + threadIdx.x;
    if (j < NL_ * BH_) {
        int row = j / (NL_ * H_);
        int col = j % (NL_ * H_);
        const float* np = noise + row * LAT_;
        const float* wp = W_lat + (size_t)col * LAT_;
        float s = b_lat[col];
        #pragma unroll 4
        for (int k = 0; k < LAT_; k++) s = fmaf(np[k], wp[k], s);
        g_hbuf[1][j] = tanhf(s);   // buffer 1 = "prev" for step 0
        g_cbuf[j] = 0.0f;
    }
    if (j < B_) { g_tok[j] = 1; g_arg[j] = 0ULL; }  // start token = 1
}

// ---------------- fused LSTM cell ----------------
// Output tile per block: 32 batch rows x 32 h-cols x 4 gates (a scattered
// 128-wide N tile over the (B,4H) gate matrix). Each thread owns 4 batch
// rows x 1 h x 4 gates => it has i,f,g,o for the same (b,h) and can apply
// the nonlinearity + state update with no extra kernel/sync.
// Smem Bs is laid out [k][h*4+gate] so the 4 gate weights are one LDS.128.
__global__ __launch_bounds__(256) void cell_kernel(
    int cb, int pb, int layer, int use_emb,
    const float* __restrict__ emb, int K1,
    const float* __restrict__ Wih, const float* __restrict__ Whh,
    const float* __restrict__ bih, const float* __restrict__ bhh)
{
    __shared__ __align__(16) float As[16][32];
    __shared__ __align__(16) float Bs[16][128];
    __shared__ int tokS[32];

    const float* hprev = &g_hbuf[pb][layer * BH_];
    const float* xin   = use_emb ? nullptr : &g_hbuf[cb][(layer - 1) * BH_];
    float* hout = &g_hbuf[cb][layer * BH_];
    float* cio  = &g_cbuf[layer * BH_];

    const int tid   = threadIdx.x;
    const int hbase = blockIdx.x * 32;
    const int mbase = blockIdx.y * 32;
    const int hl = tid & 31;    // h within tile
    const int mg = tid >> 5;    // 8 groups of 4 batch rows

    if (use_emb && tid < 32) tokS[tid] = g_tok[mbase + tid];
    __syncthreads();

    float acc[4][4];
    #pragma unroll
    for (int i = 0; i < 4; i++)
        #pragma unroll
        for (int g = 0; g < 4; g++) acc[i][g] = 0.0f;

    const int m_l = tid >> 3;          // A-load: row 0..31
    const int kk  = (tid & 7) * 2;     // A-load: 2 k's
    const int combo = tid >> 1;        // B-load: col 0..127 (== h*4+gate)
    const int kp    = tid & 1;
    const int hc = combo >> 2, gc = combo & 3;

    for (int seg = 0; seg < 2; seg++) {
        const float* W  = seg ? Whh : Wih;
        const int ldw   = seg ? H_ : K1;
        const int Ksz   = ldw;
        const float* xrow;
        if (seg == 0)
            xrow = use_emb ? (emb + (size_t)tokS[m_l] * E_)
                           : (xin + (size_t)(mbase + m_l) * K1);
        else
            xrow = hprev + (size_t)(mbase + m_l) * H_;
        const float* wrow = W + (size_t)(gc * H_ + hbase + hc) * ldw + kp * 8;

        for (int kb = 0; kb < Ksz; kb += 16) {
            float2 av = *(const float2*)(xrow + kb + kk);
            float4 w0 = *(const float4*)(wrow + kb);
            float4 w1 = *(const float4*)(wrow + kb + 4);
            As[kk][m_l]     = av.x;
            As[kk + 1][m_l] = av.y;
            const int k0 = kp * 8;
            Bs[k0 + 0][combo] = w0.x; Bs[k0 + 1][combo] = w0.y;
            Bs[k0 + 2][combo] = w0.z; Bs[k0 + 3][combo] = w0.w;
            Bs[k0 + 4][combo] = w1.x; Bs[k0 + 5][combo] = w1.y;
            Bs[k0 + 6][combo] = w1.z; Bs[k0 + 7][combo] = w1.w;
            __syncthreads();
            #pragma unroll
            for (int k = 0; k < 16; k++) {
                float4 a4 = *(const float4*)&As[k][mg * 4];
                float4 b4 = *(const float4*)&Bs[k][hl * 4];
                float a[4] = {a4.x, a4.y, a4.z, a4.w};
                float b[4] = {b4.x, b4.y, b4.z, b4.w};
                #pragma unroll
                for (int i = 0; i < 4; i++)
                    #pragma unroll
                    for (int g = 0; g < 4; g++)
                        acc[i][g] = fmaf(a[i], b[g], acc[i][g]);
            }
            __syncthreads();
        }
    }

    // gate nonlinearity + state update (torch gate order i,f,g,o)
    const int hglob = hbase + hl;
    const float bi = bih[0 * H_ + hglob] + bhh[0 * H_ + hglob];
    const float bf = bih[1 * H_ + hglob] + bhh[1 * H_ + hglob];
    const float bg = bih[2 * H_ + hglob] + bhh[2 * H_ + hglob];
    const float bo = bih[3 * H_ + hglob] + bhh[3 * H_ + hglob];
    #pragma unroll
    for (int mi = 0; mi < 4; mi++) {
        const int m = mbase + mg * 4 + mi;
        const int off = m * H_ + hglob;
        float iv = sigf(acc[mi][0] + bi);
        float fv = sigf(acc[mi][1] + bf);
        float gv = tanhf(acc[mi][2] + bg);
        float ov = sigf(acc[mi][3] + bo);
        float c2 = fmaf(fv, cio[off], iv * gv);
        float h2 = ov * tanhf(c2);
        cio[off]  = c2;
        hout[off] = h2;
    }
}

// ---------------- vocab GEMM + bias + logits store + gumbel argmax ----------------
// 128x128 output tile, K=512, 256 threads, 8x8 per thread. Fused epilogue
// writes logits to the (B,S,V)-transposed output and reduces a packed
// (ordered_float<<32 | index) max per batch row via one atomicMax per block.
__global__ __launch_bounds__(256) void biggemm_kernel(
    int cb,
    const float* __restrict__ W_fc, const float* __restrict__ b_fc,
    const float* __restrict__ gum,   // gumbel + t*B*V
    float* __restrict__ out,         // logits base (may be null)
    int t)
{
    __shared__ __align__(16) float smem[2][16][128];
    float (*As)[128] = smem[0];
    float (*Bs)[128] = smem[1];

    const float* h2 = &g_hbuf[cb][2 * BH_];
    const int tid = threadIdx.x;
    const int nbase = blockIdx.x * 128;
    const int tx = tid & 15, ty = tid >> 4;

    float acc[8][8];
    #pragma unroll
    for (int i = 0; i < 8; i++)
        #pragma unroll
        for (int j = 0; j < 8; j++) acc[i][j] = 0.0f;

    const int m_l = tid >> 1, kp = tid & 1;
    const float* aptr = h2 + (size_t)m_l * H_ + kp * 8;
    const float* bptr = W_fc + (size_t)(nbase + m_l) * H_ + kp * 8;

    for (int kb = 0; kb < H_; kb += 16) {
        float4 a0 = *(const float4*)(aptr + kb);
        float4 a1 = *(const float4*)(aptr + kb + 4);
        float4 b0 = *(const float4*)(bptr + kb);
        float4 b1 = *(const float4*)(bptr + kb + 4);
        const int k0 = kp * 8;
        As[k0+0][m_l]=a0.x; As[k0+1][m_l]=a0.y; As[k0+2][m_l]=a0.z; As[k0+3][m_l]=a0.w;
        As[k0+4][m_l]=a1.x; As[k0+5][m_l]=a1.y; As[k0+6][m_l]=a1.z; As[k0+7][m_l]=a1.w;
        Bs[k0+0][m_l]=b0.x; Bs[k0+1][m_l]=b0.y; Bs[k0+2][m_l]=b0.z; Bs[k0+3][m_l]=b0.w;
        Bs[k0+4][m_l]=b1.x; Bs[k0+5][m_l]=b1.y; Bs[k0+6][m_l]=b1.z; Bs[k0+7][m_l]=b1.w;
        __syncthreads();
        #pragma unroll
        for (int k = 0; k < 16; k++) {
            float4 u0 = *(const float4*)&As[k][ty * 8];
            float4 u1 = *(const float4*)&As[k][ty * 8 + 4];
            float4 v0 = *(const float4*)&Bs[k][tx * 8];
            float4 v1 = *(const float4*)&Bs[k][tx * 8 + 4];
            float a[8] = {u0.x,u0.y,u0.z,u0.w,u1.x,u1.y,u1.z,u1.w};
            float b[8] = {v0.x,v0.y,v0.z,v0.w,v1.x,v1.y,v1.z,v1.w};
            #pragma unroll
            for (int i = 0; i < 8; i++)
                #pragma unroll
                for (int j = 0; j < 8; j++)
                    acc[i][j] = fmaf(a[i], b[j], acc[i][j]);
        }
        __syncthreads();
    }

    float bias[8];
    #pragma unroll
    for (int j = 0; j < 8; j++) bias[j] = b_fc[nbase + tx * 8 + j];

    unsigned long long rowbest[8];
    #pragma unroll
    for (int mi = 0; mi < 8; mi++) {
        const int m = ty * 8 + mi;
        const float* gp = gum + (size_t)m * V_ + nbase + tx * 8;
        float4 g0 = *(const float4*)gp;
        float4 g1 = *(const float4*)(gp + 4);
        float v[8];
        #pragma unroll
        for (int j = 0; j < 8; j++) v[j] = acc[mi][j] + bias[j];
        if (out) {
            float* op = out + ((size_t)m * S_ + t) * V_ + nbase + tx * 8;
            *(float4*)op       = make_float4(v[0], v[1], v[2], v[3]);
            *(float4*)(op + 4) = make_float4(v[4], v[5], v[6], v[7]);
        }
        float gg[8] = {g0.x,g0.y,g0.z,g0.w,g1.x,g1.y,g1.z,g1.w};
        unsigned long long bk = 0ULL;
        #pragma unroll
        for (int j = 0; j < 8; j++) {
            float s = v[j] + gg[j];
            unsigned long long k =
                ((unsigned long long)fkey(s) << 32) | (unsigned)(nbase + tx * 8 + j);
            if (k > bk) bk = k;
        }
        rowbest[mi] = bk;
    }

    __syncthreads();
    unsigned long long* red = reinterpret_cast<unsigned long long*>(&smem[0][0][0]);
    #pragma unroll
    for (int mi = 0; mi < 8; mi++) red[(ty * 8 + mi) * 16 + tx] = rowbest[mi];
    __syncthreads();
    if (tid < B_) {
        unsigned long long bk = red[tid * 16];
        #pragma unroll
        for (int j = 1; j < 16; j++) {
            unsigned long long k = red[tid * 16 + j];
            if (k > bk) bk = k;
        }
        atomicMax(&g_arg[tid], bk);
    }
}

// ---------------- finalize: token feedback + samples output ----------------
__global__ void finalize_kernel(int t, float* __restrict__ samples_out) {
    int b = threadIdx.x;
    if (b < B_) {
        unsigned long long k = g_arg[b];
        int idx = (int)(unsigned)(k & 0xffffffffu);
        g_tok[b] = idx;
        g_arg[b] = 0ULL;
        if (samples_out) samples_out[(size_t)b * S_ + t] = (float)idx;
    }
}

// ---------------- launch ----------------
extern "C" void kernel_launch(void* const* d_in, const int* in_sizes, int n_in,
                              void* d_out, int out_size) {
    const float* noise = (const float*)d_in[0];
    const float* emb   = (const float*)d_in[1];
    const float* W_lat = (const float*)d_in[2];
    const float* b_lat = (const float*)d_in[3];
    const float* W_ih0 = (const float*)d_in[4];
    const float* W_hh0 = (const float*)d_in[5];
    const float* b_ih0 = (const float*)d_in[6];
    const float* b_hh0 = (const float*)d_in[7];
    const float* W_ihr = (const float*)d_in[8];
    const float* W_hhr = (const float*)d_in[9];
    const float* b_ihr = (const float*)d_in[10];
    const float* b_hhr = (const float*)d_in[11];
    const float* W_fc  = (const float*)d_in[12];
    const float* b_fc  = (const float*)d_in[13];
    const float* gum   = (const float*)d_in[14];
    float* out = (float*)d_out;

    const long LOGN = (long)B_ * S_ * V_;
    float* logits_out  = ((long)out_size >= LOGN) ? out : nullptr;
    float* samples_out = ((long)out_size >= LOGN + (long)B_ * S_) ? out + LOGN : nullptr;
    if ((long)out_size == (long)B_ * S_) samples_out = out;  // samples-only fallback

    init_kernel<<<(NL_ * BH_ + 255) / 256, 256>>>(noise, W_lat, b_lat);

    for (int t = 0; t < S_; t++) {
        const int cbi = t & 1, pbi = cbi ^ 1;
        dim3 cgrid(H_ / 32, B_ / 32);
        cell_kernel<<<cgrid, 256>>>(cbi, pbi, 0, 1, emb, E_,
                                    W_ih0, W_hh0, b_ih0, b_hh0);
        cell_kernel<<<cgrid, 256>>>(cbi, pbi, 1, 0, emb, H_,
                                    W_ihr, W_hhr, b_ihr, b_hhr);
        cell_kernel<<<cgrid, 256>>>(cbi, pbi, 2, 0, emb, H_,
                                    W_ihr + (size_t)4 * H_ * H_,
                                    W_hhr + (size_t)4 * H_ * H_,
                                    b_ihr + 4 * H_, b_hhr + 4 * H_);
        biggemm_kernel<<<V_ / 128, 256>>>(cbi, W_fc, b_fc,
                                          gum + (size_t)t * B_ * V_,
                                          logits_out, t);
        finalize_kernel<<<1, 128>>>(t, samples_out);
    }
}

// round 5
// speedup vs baseline: 1.1955x; 1.1955x over previous
#include <cuda_runtime.h>
#include <math.h>

// ---------------- problem constants ----------------
constexpr int V_  = 32000;
constexpr int E_  = 256;
constexpr int H_  = 512;
constexpr int LAT_= 100;
constexpr int NL_ = 3;
constexpr int B_  = 128;
constexpr int S_  = 32;
constexpr int BH_ = B_ * H_;

// ---------------- persistent device state ----------------
__device__ float g_hbuf[2][NL_ * BH_];
__device__ float g_cbuf[NL_ * BH_];
__device__ int   g_tok[B_];
__device__ unsigned long long g_arg[B_];

__device__ __forceinline__ float sigf(float x) { return 1.0f / (1.0f + expf(-x)); }

// order-preserving float -> uint transform (finite values)
__device__ __forceinline__ unsigned int fkey(float f) {
    unsigned int u = __float_as_uint(f);
    return (u & 0x80000000u) ? ~u : (u | 0x80000000u);
}

// ---------------- init: h0 = tanh(noise @ W_lat^T + b_lat) ----------------
__global__ void init_kernel(const float* __restrict__ noise,
                            const float* __restrict__ W_lat,
                            const float* __restrict__ b_lat) {
    int j = blockIdx.x * blockDim.x + threadIdx.x;
    if (j < NL_ * BH_) {
        int row = j / (NL_ * H_);
        int col = j % (NL_ * H_);
        const float* np = noise + row * LAT_;
        const float* wp = W_lat + (size_t)col * LAT_;
        float s = b_lat[col];
        #pragma unroll 4
        for (int k = 0; k < LAT_; k++) s = fmaf(np[k], wp[k], s);
        g_hbuf[1][j] = tanhf(s);   // buffer 1 = "prev" for step 0
        g_cbuf[j] = 0.0f;
    }
    if (j < B_) { g_tok[j] = 1; g_arg[j] = 0ULL; }  // start token = 1
}

// ---------------- fused LSTM cell ----------------
// Tile per block: 16 batch rows x 32 h-cols x 4 gates (128 gate-combos).
// Grid = 16 col-tiles x 8 row-tiles = 128 blocks (SM coverage).
// Register-prefetched double-buffered smem: one __syncthreads per k-iter;
// the global load for k-block i+1 is in flight during the compute of block i.
// Each thread owns 2 batch rows x 1 h x all 4 gates (i,f,g,o) -> fused
// nonlinearity + state update, no extra kernel.
__global__ __launch_bounds__(256) void cell_kernel(
    int cb, int pb, int layer, int use_emb,
    const float* __restrict__ emb, int K1,
    const float* __restrict__ Wih, const float* __restrict__ Whh,
    const float* __restrict__ bih, const float* __restrict__ bhh)
{
    __shared__ __align__(16) float As[2][16][16];
    __shared__ __align__(16) float Bs[2][16][128];
    __shared__ int tokS[16];

    const float* hprev = &g_hbuf[pb][layer * BH_];
    const float* xin   = use_emb ? nullptr : &g_hbuf[cb][(layer - 1) * BH_];
    float* hout = &g_hbuf[cb][layer * BH_];
    float* cio  = &g_cbuf[layer * BH_];

    const int tid   = threadIdx.x;
    const int hbase = blockIdx.x * 32;   // 16 tiles of 32 h
    const int mbase = blockIdx.y * 16;   // 8 tiles of 16 rows
    const int hl = tid & 31;             // h within tile
    const int mg = tid >> 5;             // 8 groups of 2 batch rows

    if (use_emb && tid < 16) tokS[tid] = g_tok[mbase + tid];
    __syncthreads();

    // loader indices
    const int arow = tid & 15, akq = tid >> 4;   // A loaders: tid < 64
    const int combo = tid >> 1, kp = tid & 1;    // B loaders: all threads
    const int hc = combo >> 2, gc = combo & 3;

    const float* xrowA = hprev;  // safe default for tid>=64
    if (tid < 64) {
        xrowA = use_emb ? emb + (size_t)tokS[arow] * E_
                        : xin + (size_t)(mbase + arow) * K1;
    }
    const float* hrowA  = hprev + (size_t)(mbase + arow) * H_;
    const float* wihrow = Wih + (size_t)(gc * H_ + hbase + hc) * K1;
    const float* whhrow = Whh + (size_t)(gc * H_ + hbase + hc) * H_;

    const int KT = K1 + H_;

    float4 aR = make_float4(0.f, 0.f, 0.f, 0.f);
    float4 bR0, bR1;
    // prefetch k-block 0 (always in segment 0)
    if (tid < 64) aR = *(const float4*)(xrowA + akq * 4);
    bR0 = *(const float4*)(wihrow + kp * 8);
    bR1 = *(const float4*)(wihrow + kp * 8 + 4);

    float acc[2][4];
    #pragma unroll
    for (int i = 0; i < 2; i++)
        #pragma unroll
        for (int g = 0; g < 4; g++) acc[i][g] = 0.0f;

    int w = 0;
    for (int kb = 0; kb < KT; kb += 16) {
        // drain prefetch regs into buffer w
        if (tid < 64) {
            As[w][akq * 4 + 0][arow] = aR.x;
            As[w][akq * 4 + 1][arow] = aR.y;
            As[w][akq * 4 + 2][arow] = aR.z;
            As[w][akq * 4 + 3][arow] = aR.w;
        }
        const int k0 = kp * 8;
        Bs[w][k0 + 0][combo] = bR0.x; Bs[w][k0 + 1][combo] = bR0.y;
        Bs[w][k0 + 2][combo] = bR0.z; Bs[w][k0 + 3][combo] = bR0.w;
        Bs[w][k0 + 4][combo] = bR1.x; Bs[w][k0 + 5][combo] = bR1.y;
        Bs[w][k0 + 6][combo] = bR1.z; Bs[w][k0 + 7][combo] = bR1.w;
        __syncthreads();

        // issue next k-block's global loads (latency hidden by compute below)
        const int nkb = kb + 16;
        if (nkb < KT) {
            if (nkb < K1) {
                if (tid < 64) aR = *(const float4*)(xrowA + nkb + akq * 4);
                bR0 = *(const float4*)(wihrow + nkb + kp * 8);
                bR1 = *(const float4*)(wihrow + nkb + kp * 8 + 4);
            } else {
                const int k2 = nkb - K1;
                if (tid < 64) aR = *(const float4*)(hrowA + k2 + akq * 4);
                bR0 = *(const float4*)(whhrow + k2 + kp * 8);
                bR1 = *(const float4*)(whhrow + k2 + kp * 8 + 4);
            }
        }

        // compute on buffer w
        #pragma unroll
        for (int k = 0; k < 16; k++) {
            float2 a2 = *(const float2*)&As[w][k][mg * 2];
            float4 b4 = *(const float4*)&Bs[w][k][hl * 4];
            acc[0][0] = fmaf(a2.x, b4.x, acc[0][0]);
            acc[0][1] = fmaf(a2.x, b4.y, acc[0][1]);
            acc[0][2] = fmaf(a2.x, b4.z, acc[0][2]);
            acc[0][3] = fmaf(a2.x, b4.w, acc[0][3]);
            acc[1][0] = fmaf(a2.y, b4.x, acc[1][0]);
            acc[1][1] = fmaf(a2.y, b4.y, acc[1][1]);
            acc[1][2] = fmaf(a2.y, b4.z, acc[1][2]);
            acc[1][3] = fmaf(a2.y, b4.w, acc[1][3]);
        }
        w ^= 1;
    }

    // gate nonlinearity + state update (torch gate order i,f,g,o)
    const int hglob = hbase + hl;
    const float bi = bih[0 * H_ + hglob] + bhh[0 * H_ + hglob];
    const float bf = bih[1 * H_ + hglob] + bhh[1 * H_ + hglob];
    const float bg = bih[2 * H_ + hglob] + bhh[2 * H_ + hglob];
    const float bo = bih[3 * H_ + hglob] + bhh[3 * H_ + hglob];
    #pragma unroll
    for (int mi = 0; mi < 2; mi++) {
        const int m = mbase + mg * 2 + mi;
        const int off = m * H_ + hglob;
        float iv = sigf(acc[mi][0] + bi);
        float fv = sigf(acc[mi][1] + bf);
        float gv = tanhf(acc[mi][2] + bg);
        float ov = sigf(acc[mi][3] + bo);
        float c2 = fmaf(fv, cio[off], iv * gv);
        float h2 = ov * tanhf(c2);
        cio[off]  = c2;
        hout[off] = h2;
    }
}

// ---------------- vocab GEMM + bias + logits store + gumbel argmax ----------------
// (measured/inferred at ~32-35 TF/s, i.e. the fp32 FMA roofline; tensor-core
//  rewrite is staged for next round once this round's ncu confirms)
__global__ __launch_bounds__(256) void biggemm_kernel(
    int cb,
    const float* __restrict__ W_fc, const float* __restrict__ b_fc,
    const float* __restrict__ gum,
    float* __restrict__ out,
    int t)
{
    __shared__ __align__(16) float smem[2][16][128];
    float (*As)[128] = smem[0];
    float (*Bs)[128] = smem[1];

    const float* h2 = &g_hbuf[cb][2 * BH_];
    const int tid = threadIdx.x;
    const int nbase = blockIdx.x * 128;
    const int tx = tid & 15, ty = tid >> 4;

    float acc[8][8];
    #pragma unroll
    for (int i = 0; i < 8; i++)
        #pragma unroll
        for (int j = 0; j < 8; j++) acc[i][j] = 0.0f;

    const int m_l = tid >> 1, kp = tid & 1;
    const float* aptr = h2 + (size_t)m_l * H_ + kp * 8;
    const float* bptr = W_fc + (size_t)(nbase + m_l) * H_ + kp * 8;

    for (int kb = 0; kb < H_; kb += 16) {
        float4 a0 = *(const float4*)(aptr + kb);
        float4 a1 = *(const float4*)(aptr + kb + 4);
        float4 b0 = *(const float4*)(bptr + kb);
        float4 b1 = *(const float4*)(bptr + kb + 4);
        const int k0 = kp * 8;
        As[k0+0][m_l]=a0.x; As[k0+1][m_l]=a0.y; As[k0+2][m_l]=a0.z; As[k0+3][m_l]=a0.w;
        As[k0+4][m_l]=a1.x; As[k0+5][m_l]=a1.y; As[k0+6][m_l]=a1.z; As[k0+7][m_l]=a1.w;
        Bs[k0+0][m_l]=b0.x; Bs[k0+1][m_l]=b0.y; Bs[k0+2][m_l]=b0.z; Bs[k0+3][m_l]=b0.w;
        Bs[k0+4][m_l]=b1.x; Bs[k0+5][m_l]=b1.y; Bs[k0+6][m_l]=b1.z; Bs[k0+7][m_l]=b1.w;
        __syncthreads();
        #pragma unroll
        for (int k = 0; k < 16; k++) {
            float4 u0 = *(const float4*)&As[k][ty * 8];
            float4 u1 = *(const float4*)&As[k][ty * 8 + 4];
            float4 v0 = *(const float4*)&Bs[k][tx * 8];
            float4 v1 = *(const float4*)&Bs[k][tx * 8 + 4];
            float a[8] = {u0.x,u0.y,u0.z,u0.w,u1.x,u1.y,u1.z,u1.w};
            float b[8] = {v0.x,v0.y,v0.z,v0.w,v1.x,v1.y,v1.z,v1.w};
            #pragma unroll
            for (int i = 0; i < 8; i++)
                #pragma unroll
                for (int j = 0; j < 8; j++)
                    acc[i][j] = fmaf(a[i], b[j], acc[i][j]);
        }
        __syncthreads();
    }

    float bias[8];
    #pragma unroll
    for (int j = 0; j < 8; j++) bias[j] = b_fc[nbase + tx * 8 + j];

    unsigned long long rowbest[8];
    #pragma unroll
    for (int mi = 0; mi < 8; mi++) {
        const int m = ty * 8 + mi;
        const float* gp = gum + (size_t)m * V_ + nbase + tx * 8;
        float4 g0 = *(const float4*)gp;
        float4 g1 = *(const float4*)(gp + 4);
        float v[8];
        #pragma unroll
        for (int j = 0; j < 8; j++) v[j] = acc[mi][j] + bias[j];
        if (out) {
            float* op = out + ((size_t)m * S_ + t) * V_ + nbase + tx * 8;
            *(float4*)op       = make_float4(v[0], v[1], v[2], v[3]);
            *(float4*)(op + 4) = make_float4(v[4], v[5], v[6], v[7]);
        }
        float gg[8] = {g0.x,g0.y,g0.z,g0.w,g1.x,g1.y,g1.z,g1.w};
        unsigned long long bk = 0ULL;
        #pragma unroll
        for (int j = 0; j < 8; j++) {
            float s = v[j] + gg[j];
            unsigned long long k =
                ((unsigned long long)fkey(s) << 32) | (unsigned)(nbase + tx * 8 + j);
            if (k > bk) bk = k;
        }
        rowbest[mi] = bk;
    }

    __syncthreads();
    unsigned long long* red = reinterpret_cast<unsigned long long*>(&smem[0][0][0]);
    #pragma unroll
    for (int mi = 0; mi < 8; mi++) red[(ty * 8 + mi) * 16 + tx] = rowbest[mi];
    __syncthreads();
    if (tid < B_) {
        unsigned long long bk = red[tid * 16];
        #pragma unroll
        for (int j = 1; j < 16; j++) {
            unsigned long long k = red[tid * 16 + j];
            if (k > bk) bk = k;
        }
        atomicMax(&g_arg[tid], bk);
    }
}

// ---------------- finalize: token feedback + samples output ----------------
__global__ void finalize_kernel(int t, float* __restrict__ samples_out) {
    int b = threadIdx.x;
    if (b < B_) {
        unsigned long long k = g_arg[b];
        int idx = (int)(unsigned)(k & 0xffffffffu);
        g_tok[b] = idx;
        g_arg[b] = 0ULL;
        if (samples_out) samples_out[(size_t)b * S_ + t] = (float)idx;
    }
}

// ---------------- launch ----------------
extern "C" void kernel_launch(void* const* d_in, const int* in_sizes, int n_in,
                              void* d_out, int out_size) {
    const float* noise = (const float*)d_in[0];
    const float* emb   = (const float*)d_in[1];
    const float* W_lat = (const float*)d_in[2];
    const float* b_lat = (const float*)d_in[3];
    const float* W_ih0 = (const float*)d_in[4];
    const float* W_hh0 = (const float*)d_in[5];
    const float* b_ih0 = (const float*)d_in[6];
    const float* b_hh0 = (const float*)d_in[7];
    const float* W_ihr = (const float*)d_in[8];
    const float* W_hhr = (const float*)d_in[9];
    const float* b_ihr = (const float*)d_in[10];
    const float* b_hhr = (const float*)d_in[11];
    const float* W_fc  = (const float*)d_in[12];
    const float* b_fc  = (const float*)d_in[13];
    const float* gum   = (const float*)d_in[14];
    float* out = (float*)d_out;

    const long LOGN = (long)B_ * S_ * V_;
    float* logits_out  = ((long)out_size >= LOGN) ? out : nullptr;
    float* samples_out = ((long)out_size >= LOGN + (long)B_ * S_) ? out + LOGN : nullptr;
    if ((long)out_size == (long)B_ * S_) samples_out = out;  // samples-only fallback

    init_kernel<<<(NL_ * BH_ + 255) / 256, 256>>>(noise, W_lat, b_lat);

    for (int t = 0; t < S_; t++) {
        const int cbi = t & 1, pbi = cbi ^ 1;
        dim3 cgrid(16, 8);   // 128 blocks
        cell_kernel<<<cgrid, 256>>>(cbi, pbi, 0, 1, emb, E_,
                                    W_ih0, W_hh0, b_ih0, b_hh0);
        cell_kernel<<<cgrid, 256>>>(cbi, pbi, 1, 0, emb, H_,
                                    W_ihr, W_hhr, b_ihr, b_hhr);
        cell_kernel<<<cgrid, 256>>>(cbi, pbi, 2, 0, emb, H_,
                                    W_ihr + (size_t)4 * H_ * H_,
                                    W_hhr + (size_t)4 * H_ * H_,
                                    b_ihr + 4 * H_, b_hhr + 4 * H_);
        biggemm_kernel<<<V_ / 128, 256>>>(cbi, W_fc, b_fc,
                                          gum + (size_t)t * B_ * V_,
                                          logits_out, t);
        finalize_kernel<<<1, 128>>>(t, samples_out);
    }
}

// round 14
// speedup vs baseline: 1.8026x; 1.5079x over previous
#include <cuda_runtime.h>
#include <cuda_bf16.h>
#include <math.h>
#include <stdint.h>

// ---------------- problem constants ----------------
constexpr int V_  = 32000;
constexpr int E_  = 256;
constexpr int H_  = 512;
constexpr int LAT_= 100;
constexpr int NL_ = 3;
constexpr int B_  = 128;
constexpr int S_  = 32;
constexpr int BH_ = B_ * H_;

constexpr int NTILE = V_ / 128;   // 250 n-tiles of 128 vocab rows
constexpr int KC    = H_ / 32;    // 16 k-chunks of 32

// ---------------- persistent device state ----------------
__device__ float g_hbuf[2][NL_ * BH_];
__device__ float g_cbuf[NL_ * BH_];
__device__ int   g_tok[B_];
__device__ unsigned long long g_arg[B_];

// bf16 hi/lo splits: W_fc (once per launch), A = h2 (per step, from cell epilogue)
// W layout: [ntile][kchunk][n(128)][k(32)] contiguous; A layout: row-major [128][512]
__device__ __align__(16) __nv_bfloat16 g_Whi[(size_t)V_ * H_];
__device__ __align__(16) __nv_bfloat16 g_Wlo[(size_t)V_ * H_];
__device__ __align__(16) __nv_bfloat16 g_Ahi[B_ * H_];
__device__ __align__(16) __nv_bfloat16 g_Alo[B_ * H_];

__device__ __forceinline__ float sigf(float x) { return 1.0f / (1.0f + expf(-x)); }

__device__ __forceinline__ unsigned int fkey(float f) {
    unsigned int u = __float_as_uint(f);
    return (u & 0x80000000u) ? ~u : (u | 0x80000000u);
}

// ---------------- PTX helpers (baseline ISA only: legal on plain sm_103) ----------------
__device__ __forceinline__ uint32_t smem_u32(const void* p) {
    uint32_t a;
    asm("{ .reg .u64 t; cvta.to.shared.u64 t, %1; cvt.u32.u64 %0, t; }" : "=r"(a) : "l"(p));
    return a;
}
__device__ __forceinline__ void ldsm4(uint32_t* r, uint32_t addr) {
    asm volatile("ldmatrix.sync.aligned.m8n8.x4.shared.b16 {%0,%1,%2,%3}, [%4];"
                 : "=r"(r[0]), "=r"(r[1]), "=r"(r[2]), "=r"(r[3]) : "r"(addr));
}
__device__ __forceinline__ void ldsm2(uint32_t* r, uint32_t addr) {
    asm volatile("ldmatrix.sync.aligned.m8n8.x2.shared.b16 {%0,%1}, [%2];"
                 : "=r"(r[0]), "=r"(r[1]) : "r"(addr));
}
__device__ __forceinline__ void mma16816(float* c, const uint32_t* a, const uint32_t* b) {
    asm volatile("mma.sync.aligned.m16n8k16.row.col.f32.bf16.bf16.f32 "
                 "{%0,%1,%2,%3}, {%4,%5,%6,%7}, {%8,%9}, {%0,%1,%2,%3};"
                 : "+f"(c[0]), "+f"(c[1]), "+f"(c[2]), "+f"(c[3])
                 : "r"(a[0]), "r"(a[1]), "r"(a[2]), "r"(a[3]), "r"(b[0]), "r"(b[1]));
}
#define CPA16(dst, src) asm volatile("cp.async.cg.shared.global [%0], [%1], 16;" :: "r"(dst), "l"(src))
#define CPA_COMMIT()    asm volatile("cp.async.commit_group;" ::: "memory")
#define CPA_WAIT(n)     asm volatile("cp.async.wait_group %0;" :: "n"(n) : "memory")

// ---------------- init: h0 = tanh(noise @ W_lat^T + b_lat) ----------------
__global__ void init_kernel(const float* __restrict__ noise,
                            const float* __restrict__ W_lat,
                            const float* __restrict__ b_lat) {
    int j = blockIdx.x * blockDim.x + threadIdx.x;
    if (j < NL_ * BH_) {
        int row = j / (NL_ * H_);
        int col = j % (NL_ * H_);
        const float* np = noise + row * LAT_;
        const float* wp = W_lat + (size_t)col * LAT_;
        float s = b_lat[col];
        #pragma unroll 4
        for (int k = 0; k < LAT_; k++) s = fmaf(np[k], wp[k], s);
        g_hbuf[1][j] = tanhf(s);
        g_cbuf[j] = 0.0f;
    }
    if (j < B_) { g_tok[j] = 1; g_arg[j] = 0ULL; }
}

// ---------------- W_fc -> bf16 hi/lo tile images ----------------
// dst layout: [(ntile*KC + kc)*128 + nloc]*32 + kk  (cp.async-friendly 64B rows)
__global__ void convw_kernel(const float* __restrict__ W_fc) {
    int j = blockIdx.x * blockDim.x + threadIdx.x;
    if (j >= V_ * H_) return;
    int n = j >> 9;
    int k = j & 511;
    float w = W_fc[j];
    __nv_bfloat16 hv = __float2bfloat16(w);
    float lo = w - __bfloat162float(hv);
    int ntile = n >> 7, nloc = n & 127;
    int kc = k >> 5, kk = k & 31;
    size_t off = (((size_t)(ntile * KC + kc) * 128 + nloc) << 5) + kk;
    g_Whi[off] = hv;
    g_Wlo[off] = __float2bfloat16(lo);
}

// ---------------- fused LSTM cell (layer2 also emits bf16 hi/lo A) ----------------
__global__ __launch_bounds__(256) void cell_kernel(
    int cb, int pb, int layer, int use_emb, int write_a,
    const float* __restrict__ emb, int K1,
    const float* __restrict__ Wih, const float* __restrict__ Whh,
    const float* __restrict__ bih, const float* __restrict__ bhh)
{
    __shared__ __align__(16) float As[2][16][16];
    __shared__ __align__(16) float Bs[2][16][128];
    __shared__ int tokS[16];

    const float* hprev = &g_hbuf[pb][layer * BH_];
    const float* xin   = use_emb ? nullptr : &g_hbuf[cb][(layer - 1) * BH_];
    float* hout = &g_hbuf[cb][layer * BH_];
    float* cio  = &g_cbuf[layer * BH_];

    const int tid   = threadIdx.x;
    const int hbase = blockIdx.x * 32;
    const int mbase = blockIdx.y * 16;
    const int hl = tid & 31;
    const int mg = tid >> 5;

    if (use_emb && tid < 16) tokS[tid] = g_tok[mbase + tid];
    __syncthreads();

    const int arow = tid & 15, akq = tid >> 4;
    const int combo = tid >> 1, kp = tid & 1;
    const int hc = combo >> 2, gc = combo & 3;

    const float* xrowA = hprev;
    if (tid < 64) {
        xrowA = use_emb ? emb + (size_t)tokS[arow] * E_
                        : xin + (size_t)(mbase + arow) * K1;
    }
    const float* hrowA  = hprev + (size_t)(mbase + arow) * H_;
    const float* wihrow = Wih + (size_t)(gc * H_ + hbase + hc) * K1;
    const float* whhrow = Whh + (size_t)(gc * H_ + hbase + hc) * H_;

    const int KT = K1 + H_;

    float4 aR = make_float4(0.f, 0.f, 0.f, 0.f);
    float4 bR0, bR1;
    if (tid < 64) aR = *(const float4*)(xrowA + akq * 4);
    bR0 = *(const float4*)(wihrow + kp * 8);
    bR1 = *(const float4*)(wihrow + kp * 8 + 4);

    float acc[2][4];
    #pragma unroll
    for (int i = 0; i < 2; i++)
        #pragma unroll
        for (int g = 0; g < 4; g++) acc[i][g] = 0.0f;

    int w = 0;
    for (int kb = 0; kb < KT; kb += 16) {
        if (tid < 64) {
            As[w][akq * 4 + 0][arow] = aR.x;
            As[w][akq * 4 + 1][arow] = aR.y;
            As[w][akq * 4 + 2][arow] = aR.z;
            As[w][akq * 4 + 3][arow] = aR.w;
        }
        const int k0 = kp * 8;
        Bs[w][k0 + 0][combo] = bR0.x; Bs[w][k0 + 1][combo] = bR0.y;
        Bs[w][k0 + 2][combo] = bR0.z; Bs[w][k0 + 3][combo] = bR0.w;
        Bs[w][k0 + 4][combo] = bR1.x; Bs[w][k0 + 5][combo] = bR1.y;
        Bs[w][k0 + 6][combo] = bR1.z; Bs[w][k0 + 7][combo] = bR1.w;
        __syncthreads();

        const int nkb = kb + 16;
        if (nkb < KT) {
            if (nkb < K1) {
                if (tid < 64) aR = *(const float4*)(xrowA + nkb + akq * 4);
                bR0 = *(const float4*)(wihrow + nkb + kp * 8);
                bR1 = *(const float4*)(wihrow + nkb + kp * 8 + 4);
            } else {
                const int k2 = nkb - K1;
                if (tid < 64) aR = *(const float4*)(hrowA + k2 + akq * 4);
                bR0 = *(const float4*)(whhrow + k2 + kp * 8);
                bR1 = *(const float4*)(whhrow + k2 + kp * 8 + 4);
            }
        }

        #pragma unroll
        for (int k = 0; k < 16; k++) {
            float2 a2 = *(const float2*)&As[w][k][mg * 2];
            float4 b4 = *(const float4*)&Bs[w][k][hl * 4];
            acc[0][0] = fmaf(a2.x, b4.x, acc[0][0]);
            acc[0][1] = fmaf(a2.x, b4.y, acc[0][1]);
            acc[0][2] = fmaf(a2.x, b4.z, acc[0][2]);
            acc[0][3] = fmaf(a2.x, b4.w, acc[0][3]);
            acc[1][0] = fmaf(a2.y, b4.x, acc[1][0]);
            acc[1][1] = fmaf(a2.y, b4.y, acc[1][1]);
            acc[1][2] = fmaf(a2.y, b4.z, acc[1][2]);
            acc[1][3] = fmaf(a2.y, b4.w, acc[1][3]);
        }
        w ^= 1;
    }

    const int hglob = hbase + hl;
    const float bi = bih[0 * H_ + hglob] + bhh[0 * H_ + hglob];
    const float bf = bih[1 * H_ + hglob] + bhh[1 * H_ + hglob];
    const float bg = bih[2 * H_ + hglob] + bhh[2 * H_ + hglob];
    const float bo = bih[3 * H_ + hglob] + bhh[3 * H_ + hglob];
    #pragma unroll
    for (int mi = 0; mi < 2; mi++) {
        const int m = mbase + mg * 2 + mi;
        const int off = m * H_ + hglob;
        float iv = sigf(acc[mi][0] + bi);
        float fv = sigf(acc[mi][1] + bf);
        float gv = tanhf(acc[mi][2] + bg);
        float ov = sigf(acc[mi][3] + bo);
        float c2 = fmaf(fv, cio[off], iv * gv);
        float h2 = ov * tanhf(c2);
        cio[off]  = c2;
        hout[off] = h2;
        if (write_a) {
            __nv_bfloat16 hv = __float2bfloat16(h2);
            float lo = h2 - __bfloat162float(hv);
            g_Ahi[off] = hv;
            g_Alo[off] = __float2bfloat16(lo);
        }
    }
}

// ---------------- HMMA vocab GEMM + bias + logits + gumbel argmax ----------------
// CTA: 128 (batch) x 128 (vocab rows), K=512, bf16 3-term split, fp32 accum.
// 8 warps = 2 (M) x 4 (N); warp tile 64x32. cp.async double-buffered stages.
constexpr int LDA  = 40;                    // bf16 elems per smem row (pad 32->40)
constexpr int ARRB = 128 * LDA * 2;         // 10240 B per array
constexpr int STG  = 4 * ARRB;              // Ahi,Alo,Bhi,Blo per stage = 40960 B
constexpr int SM_BEST = 2 * STG;            // 81920: u64[128]
constexpr int SM_TOTAL = SM_BEST + 128 * 8;

__global__ __launch_bounds__(256) void biggemm_mma(
    const float* __restrict__ b_fc,
    const float* __restrict__ gum,    // gumbel + t*B*V
    float* __restrict__ out,          // logits base (may be null)
    int t)
{
    extern __shared__ __align__(16) char dsm[];
    const uint32_t smb = smem_u32(dsm);
    const int tid = threadIdx.x;
    const int wid = tid >> 5, lane = tid & 31;
    const int warpM = wid & 1, warpN = wid >> 1;
    const int ntile = blockIdx.x;
    const int nbase = ntile * 128;

    unsigned long long* sbest = (unsigned long long*)(dsm + SM_BEST);
    if (tid < 128) sbest[tid] = 0ULL;

    // per-lane ldmatrix base addresses
    const int aRow = warpM * 64 + (lane & 7) + ((lane >> 3) & 1) * 8;
    const int aK   = ((lane >> 4) & 1) * 8;
    const uint32_t aBase = smb + (uint32_t)(aRow * LDA + aK) * 2;
    const int bl   = lane & 15;
    const int bRow = warpN * 32 + (bl & 7);
    const int bK   = ((bl >> 3) & 1) * 8;
    const uint32_t bBase = smb + 2 * ARRB + (uint32_t)(bRow * LDA + bK) * 2;

    const size_t wtile = ((size_t)ntile * KC) << 12;  // *KC*128*32

    // stage loader: 2048 x 16B chunks (A hi/lo 512 each, B hi/lo 512 each)
    auto load_stage = [&](int stage, int kc) {
        const uint32_t sdst = smb + stage * STG;
        #pragma unroll
        for (int i = 0; i < 8; i++) {
            int c = tid + i * 256;
            int arr = c >> 9, idx = c & 511;
            int row = idx >> 2, seg = idx & 3;
            uint32_t dst = sdst + arr * ARRB + (uint32_t)(row * LDA + seg * 8) * 2;
            const __nv_bfloat16* src;
            if (arr == 0)      src = g_Ahi + row * H_ + kc * 32 + seg * 8;
            else if (arr == 1) src = g_Alo + row * H_ + kc * 32 + seg * 8;
            else if (arr == 2) src = g_Whi + wtile + ((size_t)kc * 128 + row) * 32 + seg * 8;
            else               src = g_Wlo + wtile + ((size_t)kc * 128 + row) * 32 + seg * 8;
            CPA16(dst, src);
        }
    };

    float acc[4][4][4];
    #pragma unroll
    for (int mf = 0; mf < 4; mf++)
        #pragma unroll
        for (int nf = 0; nf < 4; nf++)
            #pragma unroll
            for (int i = 0; i < 4; i++) acc[mf][nf][i] = 0.0f;

    load_stage(0, 0);
    CPA_COMMIT();

    for (int kc = 0; kc < KC; kc++) {
        if (kc + 1 < KC) {
            load_stage((kc + 1) & 1, kc + 1);
            CPA_COMMIT();
            CPA_WAIT(1);
        } else {
            CPA_WAIT(0);
        }
        __syncthreads();

        const uint32_t soff = (kc & 1) * STG;
        #pragma unroll
        for (int k16 = 0; k16 < 2; k16++) {
            const uint32_t kb2 = (uint32_t)(k16 * 16) * 2;
            uint32_t bhi[4][2], blo[4][2];
            #pragma unroll
            for (int nf = 0; nf < 4; nf++) {
                uint32_t ba = bBase + soff + (uint32_t)(nf * 8 * LDA) * 2 + kb2;
                ldsm2(bhi[nf], ba);
                ldsm2(blo[nf], ba + ARRB);
            }
            uint32_t ahi[4][4], alo[4][4];
            #pragma unroll
            for (int mf = 0; mf < 4; mf++) {
                uint32_t aa = aBase + soff + (uint32_t)(mf * 16 * LDA) * 2 + kb2;
                ldsm4(ahi[mf], aa);
                ldsm4(alo[mf], aa + ARRB);
            }
            #pragma unroll
            for (int mf = 0; mf < 4; mf++)
                #pragma unroll
                for (int nf = 0; nf < 4; nf++) {
                    mma16816(acc[mf][nf], ahi[mf], bhi[nf]);
                    mma16816(acc[mf][nf], ahi[mf], blo[nf]);
                    mma16816(acc[mf][nf], alo[mf], bhi[nf]);
                }
        }
        __syncthreads();
    }

    // ---- fused epilogue: bias + logits store + gumbel argmax ----
    const int tq = lane & 3, gid = lane >> 2;
    float2 bz[4];
    #pragma unroll
    for (int nf = 0; nf < 4; nf++)
        bz[nf] = *(const float2*)&b_fc[nbase + warpN * 32 + nf * 8 + 2 * tq];

    #pragma unroll
    for (int mf = 0; mf < 4; mf++) {
        #pragma unroll
        for (int half = 0; half < 2; half++) {
            const int r = warpM * 64 + mf * 16 + gid + half * 8;
            unsigned long long bk = 0ULL;
            #pragma unroll
            for (int nf = 0; nf < 4; nf++) {
                const int col = nbase + warpN * 32 + nf * 8 + 2 * tq;
                float v0 = acc[mf][nf][half * 2 + 0] + bz[nf].x;
                float v1 = acc[mf][nf][half * 2 + 1] + bz[nf].y;
                if (out) *(float2*)&out[((size_t)r * S_ + t) * V_ + col] = make_float2(v0, v1);
                float2 g = *(const float2*)&gum[(size_t)r * V_ + col];
                unsigned long long k0 = ((unsigned long long)fkey(v0 + g.x) << 32) | (unsigned)col;
                unsigned long long k1 = ((unsigned long long)fkey(v1 + g.y) << 32) | (unsigned)(col + 1);
                if (k0 > bk) bk = k0;
                if (k1 > bk) bk = k1;
            }
            #pragma unroll
            for (int m = 2; m >= 1; m >>= 1) {
                unsigned long long o = __shfl_xor_sync(0xffffffffu, bk, m);
                if (o > bk) bk = o;
            }
            if (tq == 0) atomicMax(&sbest[r], bk);
        }
    }
    __syncthreads();
    if (tid < 128) atomicMax(&g_arg[tid], sbest[tid]);
}

// ---------------- finalize: token feedback + samples output ----------------
__global__ void finalize_kernel(int t, float* __restrict__ samples_out) {
    int b = threadIdx.x;
    if (b < B_) {
        unsigned long long k = g_arg[b];
        int idx = (int)(unsigned)(k & 0xffffffffu);
        g_tok[b] = idx;
        g_arg[b] = 0ULL;
        if (samples_out) samples_out[(size_t)b * S_ + t] = (float)idx;
    }
}

// ---------------- launch ----------------
extern "C" void kernel_launch(void* const* d_in, const int* in_sizes, int n_in,
                              void* d_out, int out_size) {
    const float* noise = (const float*)d_in[0];
    const float* emb   = (const float*)d_in[1];
    const float* W_lat = (const float*)d_in[2];
    const float* b_lat = (const float*)d_in[3];
    const float* W_ih0 = (const float*)d_in[4];
    const float* W_hh0 = (const float*)d_in[5];
    const float* b_ih0 = (const float*)d_in[6];
    const float* b_hh0 = (const float*)d_in[7];
    const float* W_ihr = (const float*)d_in[8];
    const float* W_hhr = (const float*)d_in[9];
    const float* b_ihr = (const float*)d_in[10];
    const float* b_hhr = (const float*)d_in[11];
    const float* W_fc  = (const float*)d_in[12];
    const float* b_fc  = (const float*)d_in[13];
    const float* gum   = (const float*)d_in[14];
    float* out = (float*)d_out;

    const long LOGN = (long)B_ * S_ * V_;
    float* logits_out  = ((long)out_size >= LOGN) ? out : nullptr;
    float* samples_out = ((long)out_size >= LOGN + (long)B_ * S_) ? out + LOGN : nullptr;
    if ((long)out_size == (long)B_ * S_) samples_out = out;

    cudaFuncSetAttribute(biggemm_mma, cudaFuncAttributeMaxDynamicSharedMemorySize, SM_TOTAL);

    init_kernel<<<(NL_ * BH_ + 255) / 256, 256>>>(noise, W_lat, b_lat);
    convw_kernel<<<(V_ * H_ + 255) / 256, 256>>>(W_fc);

    for (int t = 0; t < S_; t++) {
        const int cbi = t & 1, pbi = cbi ^ 1;
        dim3 cgrid(16, 8);
        cell_kernel<<<cgrid, 256>>>(cbi, pbi, 0, 1, 0, emb, E_,
                                    W_ih0, W_hh0, b_ih0, b_hh0);
        cell_kernel<<<cgrid, 256>>>(cbi, pbi, 1, 0, 0, emb, H_,
                                    W_ihr, W_hhr, b_ihr, b_hhr);
        cell_kernel<<<cgrid, 256>>>(cbi, pbi, 2, 0, 1, emb, H_,
                                    W_ihr + (size_t)4 * H_ * H_,
                                    W_hhr + (size_t)4 * H_ * H_,
                                    b_ihr + 4 * H_, b_hhr + 4 * H_);
        biggemm_mma<<<NTILE, 256, SM_TOTAL>>>(b_fc, gum + (size_t)t * B_ * V_,
                                              logits_out, t);
        finalize_kernel<<<1, 128>>>(t, samples_out);
    }
}